// round 7
// baseline (speedup 1.0000x reference)
#include <cuda_runtime.h>
#include <cuda_bf16.h>

// ConservativeCrossEntropyLoss: loss_i = logsumexp(x_i) - (sum_j w[t_i][j] * x_ij) / S(t_i)
// w[t][j] = 0.7 (j==t), base + 0.2*2^{t-j} (j>t), base (j<t);  base = 0.1/9
// S(t) = 0.7 + 8*base + 0.2*(1 - 2^{t-8})
// out = mean(loss)

#define TPB 256
#define C 9
#define MAX_GRID 2048

__device__ float g_partials[MAX_GRID];

__global__ __launch_bounds__(TPB) void cce_main_kernel(
    const float* __restrict__ logits,
    const int*   __restrict__ targets,
    int n)
{
    constexpr float BASE   = 0.1f / 9.0f;
    constexpr float MAIN_W = 1.0f - 0.1f - 0.2f;   // 0.7

    __shared__ __align__(16) float tile[TPB * C];   // 9216 B
    __shared__ float s_invS[C];
    __shared__ float s_red[TPB / 32];

    if (threadIdx.x < C) {
        int t = threadIdx.x;
        float p = __int_as_float((127 + t - 8) << 23);   // 2^(t-8), exact
        float S = MAIN_W + 8.0f * BASE + 0.2f * (1.0f - p);
        s_invS[t] = 1.0f / S;
    }

    float acc = 0.0f;
    const int numTiles = (n + TPB - 1) / TPB;

    for (int tileIdx = blockIdx.x; tileIdx < numTiles; tileIdx += gridDim.x) {
        const int base = tileIdx * TPB;
        const int rows = min(TPB, n - base);

        __syncthreads();   // smem reuse fence (also orders s_invS init before first use)

        // ---- stage: coalesced global -> smem ----
        const float* gsrc = logits + (size_t)base * C;
        const int nf = rows * C;
        if ((nf & 3) == 0) {
            const float4* __restrict__ g4 = (const float4*)gsrc;
            float4* s4 = (float4*)tile;
            #pragma unroll 3
            for (int i = threadIdx.x; i < (nf >> 2); i += TPB)
                s4[i] = g4[i];
        } else {
            for (int i = threadIdx.x; i < nf; i += TPB)
                tile[i] = gsrc[i];
        }
        __syncthreads();

        // ---- compute: one row per thread ----
        if (threadIdx.x < rows) {
            const int row = base + threadIdx.x;
            float x[C];
            #pragma unroll
            for (int j = 0; j < C; j++) x[j] = tile[threadIdx.x * C + j];

            float m = x[0];
            #pragma unroll
            for (int j = 1; j < C; j++) m = fmaxf(m, x[j]);

            float s = 0.0f;
            #pragma unroll
            for (int j = 0; j < C; j++) s += __expf(x[j] - m);
            const float lse = m + __logf(s);

            const int t = targets[row];
            float dot = 0.0f;
            #pragma unroll
            for (int j = 0; j < C; j++) {
                const int d = j - t;
                // 2^{-d} for d>0 via exponent-field construction (pure ALU, exact)
                const float up = 0.2f * __int_as_float((127 - d) << 23);
                float w = (d > 0) ? (BASE + up) : BASE;
                w = (d == 0) ? MAIN_W : w;
                dot = fmaf(w, x[j], dot);
            }
            acc += lse - dot * s_invS[t];
        }
    }

    // ---- block reduce (deterministic order) ----
    #pragma unroll
    for (int o = 16; o > 0; o >>= 1)
        acc += __shfl_xor_sync(0xFFFFFFFFu, acc, o);

    const int wid  = threadIdx.x >> 5;
    const int lane = threadIdx.x & 31;
    if (lane == 0) s_red[wid] = acc;
    __syncthreads();
    if (wid == 0) {
        float v = (lane < TPB / 32) ? s_red[lane] : 0.0f;
        #pragma unroll
        for (int o = 4; o > 0; o >>= 1)
            v += __shfl_xor_sync(0xFFFFFFFFu, v, o);
        if (lane == 0) g_partials[blockIdx.x] = v;
    }
}

__global__ __launch_bounds__(TPB) void cce_finalize_kernel(
    float* __restrict__ out, int nblocks, int n)
{
    __shared__ double s_red[TPB / 32];

    double s = 0.0;
    for (int i = threadIdx.x; i < nblocks; i += TPB)
        s += (double)g_partials[i];

    #pragma unroll
    for (int o = 16; o > 0; o >>= 1)
        s += __shfl_xor_sync(0xFFFFFFFFu, s, o);

    const int wid  = threadIdx.x >> 5;
    const int lane = threadIdx.x & 31;
    if (lane == 0) s_red[wid] = s;
    __syncthreads();
    if (wid == 0) {
        double v = (lane < TPB / 32) ? s_red[lane] : 0.0;
        #pragma unroll
        for (int o = 4; o > 0; o >>= 1)
            v += __shfl_xor_sync(0xFFFFFFFFu, v, o);
        if (lane == 0) out[0] = (float)(v / (double)n);
    }
}

extern "C" void kernel_launch(void* const* d_in, const int* in_sizes, int n_in,
                              void* d_out, int out_size)
{
    const float* logits  = (const float*)d_in[0];
    const int*   targets = (const int*)d_in[1];
    const int n = in_sizes[1];                 // number of rows (targets count)

    const int numTiles = (n + TPB - 1) / TPB;  // 15625 for n=4e6
    int grid = 148 * 8;                        // 1184 persistent-ish blocks
    if (grid > numTiles) grid = numTiles;
    if (grid > MAX_GRID) grid = MAX_GRID;

    cce_main_kernel<<<grid, TPB>>>(logits, targets, n);
    cce_finalize_kernel<<<1, TPB>>>((float*)d_out, grid, n);
}